// round 8
// baseline (speedup 1.0000x reference)
#include <cuda_runtime.h>

// Problem dims (fixed by the reference)
#define Bn  4
#define Qn  256
#define KVn 1024
#define Hn  128
#define VSn 256

#define KPB 128   // keys per score-kernel block (KVn/KPB chunks)

// Scratch (no cudaMalloc allowed)
__device__ float g_Eq[Bn * Qn * Hn];       // e^{2*clamp(q_proj)}
__device__ float g_Ek[Bn * KVn * Hn];      // e^{2*clamp(k_proj)}
__device__ float g_scores[Bn * Qn * KVn];  // raw additive scores

// 2*log2(e): e^{2x} = 2^{x * 2*log2(e)}
#define TWO_LOG2E 2.885390081777927f

// ---------------------------------------------------------------------------
// Kernel 1: project rows and emit E = exp2(clamp(proj, +-40) * 2*log2(e)).
// ---------------------------------------------------------------------------
__global__ void proj_kernel(const float* __restrict__ queries,
                            const float* __restrict__ keys,
                            const float* __restrict__ Wq,
                            const float* __restrict__ Wk) {
    const int r0 = blockIdx.x * 8;
    const float* in;
    const float* W;
    float* outp;
    if (r0 < Bn * Qn) {
        in   = queries + r0 * Hn;
        W    = Wq;
        outp = g_Eq + r0 * Hn;
    } else {
        const int rr = r0 - Bn * Qn;
        in   = keys + rr * Hn;
        W    = Wk;
        outp = g_Ek + rr * Hn;
    }
    __shared__ float s[8][Hn];
    const int t = threadIdx.x;
    #pragma unroll
    for (int rr = 0; rr < 8; rr++) s[rr][t] = in[rr * Hn + t];
    __syncthreads();

    float a[8];
    #pragma unroll
    for (int rr = 0; rr < 8; rr++) a[rr] = 0.f;

    #pragma unroll 4
    for (int kk = 0; kk < Hn; kk++) {
        const float w = W[kk * Hn + t];
        #pragma unroll
        for (int rr = 0; rr < 8; rr++)
            a[rr] = fmaf(s[rr][kk], w, a[rr]);
    }
    #pragma unroll
    for (int rr = 0; rr < 8; rr++) {
        float p = fminf(fmaxf(a[rr], -40.f), 40.f) * TWO_LOG2E;
        float e;
        asm("ex2.approx.f32 %0, %1;" : "=f"(e) : "f"(p));
        outp[rr * Hn + t] = e;
    }
}

// ---------------------------------------------------------------------------
// Kernel 2 (scores): grid (Bn*Qn/2, KVn/KPB), 256 threads.
// Block = (query pair, key chunk). Early-exits past valid_len.
// 8-lane-per-key geometry: sub=lane>>3 picks key of quad, hb=(lane&7)*16 the
// h-chunk. tanh(x) = 1 - 2/(Eq*Ek + 1); Sum_h w_h hoisted.
// MUFU halved by pairing: w0/d0 + w1/d1 = (w0*d1c + w1*d0c) * rcp(d0c*d1c),
// with d clamped at 1e18 (term < 3e-18 there, so clamping is exact-enough and
// keeps every product finite).
// ---------------------------------------------------------------------------
__global__ void score_kernel(const int* __restrict__ valid_lens,
                             const float* __restrict__ wv) {
    const int pair  = blockIdx.x;            // [0, 512)
    const int chunk = blockIdx.y;            // [0, KVn/KPB)
    const int b     = pair >> 7;             // 128 pairs per batch
    const int row0  = (b << 8) + ((pair & 127) << 1);
    const int row1  = row0 + 1;

    const int L = valid_lens[b];
    if (L <= 0) return;                      // uniform case handled downstream
    const int jbeg = chunk * KPB;
    if (jbeg >= L) return;
    const int jend = (jbeg + KPB < L) ? (jbeg + KPB) : L;

    const int tid  = threadIdx.x;
    const int lane = tid & 31;
    const int warp = tid >> 5;
    const int sub  = lane >> 3;
    const int hb   = (lane & 7) << 4;

    float4 qa[4], qb[4], w2[4];
    float wsum_l = 0.f;
    #pragma unroll
    for (int i = 0; i < 4; i++) {
        qa[i] = *reinterpret_cast<const float4*>(&g_Eq[row0 * Hn + hb + i * 4]);
        qb[i] = *reinterpret_cast<const float4*>(&g_Eq[row1 * Hn + hb + i * 4]);
        float4 w = *reinterpret_cast<const float4*>(&wv[hb + i * 4]);
        wsum_l += ((w.x + w.y) + (w.z + w.w));
        w2[i] = make_float4(-2.f * w.x, -2.f * w.y, -2.f * w.z, -2.f * w.w);
    }
    const float* kb = g_Ek + b * KVn * Hn;

    for (int j0 = jbeg + warp * 4; j0 < jend; j0 += 32) {
        const int key = j0 + sub;
        const int kc  = (key < jend) ? key : (jend - 1);  // clamp (safe load)

        float4 k4[4];
        #pragma unroll
        for (int i = 0; i < 4; i++)
            k4[i] = *reinterpret_cast<const float4*>(&kb[kc * Hn + hb + i * 4]);

        float s0 = wsum_l, s1 = 0.f, t0 = wsum_l, t1 = 0.f;
        #pragma unroll
        for (int i = 0; i < 4; i++) {
            // row0
            float d0 = fminf(fmaf(qa[i].x, k4[i].x, 1.f), 1e18f);
            float d1 = fminf(fmaf(qa[i].y, k4[i].y, 1.f), 1e18f);
            float d2 = fminf(fmaf(qa[i].z, k4[i].z, 1.f), 1e18f);
            float d3 = fminf(fmaf(qa[i].w, k4[i].w, 1.f), 1e18f);
            float n01 = fmaf(w2[i].x, d1, w2[i].y * d0);
            float n23 = fmaf(w2[i].z, d3, w2[i].w * d2);
            float r01, r23;
            asm("rcp.approx.f32 %0, %1;" : "=f"(r01) : "f"(d0 * d1));
            asm("rcp.approx.f32 %0, %1;" : "=f"(r23) : "f"(d2 * d3));
            s0 = fmaf(n01, r01, s0);
            s1 = fmaf(n23, r23, s1);
            // row1
            float e0 = fminf(fmaf(qb[i].x, k4[i].x, 1.f), 1e18f);
            float e1 = fminf(fmaf(qb[i].y, k4[i].y, 1.f), 1e18f);
            float e2 = fminf(fmaf(qb[i].z, k4[i].z, 1.f), 1e18f);
            float e3 = fminf(fmaf(qb[i].w, k4[i].w, 1.f), 1e18f);
            float m01 = fmaf(w2[i].x, e1, w2[i].y * e0);
            float m23 = fmaf(w2[i].z, e3, w2[i].w * e2);
            float u01, u23;
            asm("rcp.approx.f32 %0, %1;" : "=f"(u01) : "f"(e0 * e1));
            asm("rcp.approx.f32 %0, %1;" : "=f"(u23) : "f"(e2 * e3));
            t0 = fmaf(m01, u01, t0);
            t1 = fmaf(m23, u23, t1);
        }
        float s = s0 + s1;
        float t = t0 + t1;

        // reduce across the 8 lanes of each key group
        s += __shfl_xor_sync(0xffffffffu, s, 1);
        t += __shfl_xor_sync(0xffffffffu, t, 1);
        s += __shfl_xor_sync(0xffffffffu, s, 2);
        t += __shfl_xor_sync(0xffffffffu, t, 2);
        s += __shfl_xor_sync(0xffffffffu, s, 4);
        t += __shfl_xor_sync(0xffffffffu, t, 4);

        if ((lane & 7) == 0 && key < jend) {
            g_scores[row0 * KVn + key] = s;
            g_scores[row1 * KVn + key] = t;
        }
    }
}

// ---------------------------------------------------------------------------
// Kernel 3 (softmax + AV): grid 512 pairs, 256 threads. Light on registers ->
// high occupancy, single wave. Matches the -1e6 masking semantics;
// valid_len == 0 degenerates to uniform weights over all KV.
// ---------------------------------------------------------------------------
__global__ void softmax_av_kernel(const float* __restrict__ values,
                                  const int* __restrict__ valid_lens,
                                  float* __restrict__ out) {
    const int pair = blockIdx.x;
    const int b    = pair >> 7;
    const int row0 = (b << 8) + ((pair & 127) << 1);
    const int row1 = row0 + 1;
    const int tid  = threadIdx.x;
    const int lane = tid & 31;
    const int warp = tid >> 5;

    __shared__ float s_sc[2][KVn];
    __shared__ float s_red[2][8];

    const int L     = valid_lens[b];
    const bool uni  = (L <= 0);
    const int effL  = uni ? KVn : L;

    float Z0, Z1;
    if (!uni) {
        // load raw scores
        for (int jj = tid; jj < effL; jj += 256) {
            s_sc[0][jj] = g_scores[row0 * KVn + jj];
            s_sc[1][jj] = g_scores[row1 * KVn + jj];
        }
        __syncthreads();

        // max per row
        #pragma unroll
        for (int r = 0; r < 2; r++) {
            float m = -3.0e38f;
            for (int jj = tid; jj < effL; jj += 256) m = fmaxf(m, s_sc[r][jj]);
            #pragma unroll
            for (int o = 16; o > 0; o >>= 1)
                m = fmaxf(m, __shfl_xor_sync(0xffffffffu, m, o));
            if (lane == 0) s_red[r][warp] = m;
        }
        __syncthreads();
        #pragma unroll
        for (int r = 0; r < 2; r++) {
            float M = s_red[r][0];
            #pragma unroll
            for (int k = 1; k < 8; k++) M = fmaxf(M, s_red[r][k]);

            float z = 0.f;
            for (int jj = tid; jj < effL; jj += 256) {
                const float e = __expf(s_sc[r][jj] - M);
                s_sc[r][jj] = e;
                z += e;
            }
            #pragma unroll
            for (int o = 16; o > 0; o >>= 1)
                z += __shfl_xor_sync(0xffffffffu, z, o);
            if (lane == 0) s_red[r][warp] = z;
        }
        __syncthreads();
        Z0 = s_red[0][0]; Z1 = s_red[1][0];
        #pragma unroll
        for (int k = 1; k < 8; k++) {
            Z0 += s_red[0][k];
            Z1 += s_red[1][k];
        }
    } else {
        for (int jj = tid; jj < KVn; jj += 256) {
            s_sc[0][jj] = 1.0f;
            s_sc[1][jj] = 1.0f;
        }
        __syncthreads();
        Z0 = (float)KVn;
        Z1 = (float)KVn;
    }

    // AV: thread owns column tid; each V element feeds both rows.
    const int c = tid;
    const float* vb = values + (size_t)b * KVn * VSn + c;
    float a0[4], a1[4];
    #pragma unroll
    for (int u = 0; u < 4; u++) { a0[u] = 0.f; a1[u] = 0.f; }

    int j = 0;
    for (; j + 4 <= effL; j += 4) {
        #pragma unroll
        for (int u = 0; u < 4; u++) {
            const float v = vb[(j + u) * VSn];
            a0[u] = fmaf(s_sc[0][j + u], v, a0[u]);
            a1[u] = fmaf(s_sc[1][j + u], v, a1[u]);
        }
    }
    for (; j < effL; j++) {
        const float v = vb[j * VSn];
        a0[0] = fmaf(s_sc[0][j], v, a0[0]);
        a1[0] = fmaf(s_sc[1][j], v, a1[0]);
    }

    out[row0 * VSn + c] = ((a0[0] + a0[1]) + (a0[2] + a0[3])) / Z0;
    out[row1 * VSn + c] = ((a1[0] + a1[1]) + (a1[2] + a1[3])) / Z1;
}

// ---------------------------------------------------------------------------
extern "C" void kernel_launch(void* const* d_in, const int* in_sizes, int n_in,
                              void* d_out, int out_size) {
    const float* queries = (const float*)d_in[0];
    const float* keys    = (const float*)d_in[1];
    const float* values  = (const float*)d_in[2];
    const int*   valid   = (const int*)d_in[3];
    const float* Wq      = (const float*)d_in[4];
    const float* Wk      = (const float*)d_in[5];
    const float* wv      = (const float*)d_in[6];
    float* out           = (float*)d_out;

    proj_kernel<<<(Bn * Qn + Bn * KVn) / 8, 128>>>(queries, keys, Wq, Wk);

    dim3 sgrid(Bn * Qn / 2, KVn / KPB);
    score_kernel<<<sgrid, 256>>>(valid, wv);

    softmax_av_kernel<<<Bn * Qn / 2, 256>>>(values, valid, out);
}